// round 1
// baseline (speedup 1.0000x reference)
#include <cuda_runtime.h>
#include <math.h>

#define B_   2
#define N_   4096
#define E_   1024
#define H_   16
#define HD_  64
#define BH_  32
#define M_   8192

// ---------------- device scratch (no allocations allowed) ----------------
__device__ float g_weff[4][E_ * E_];          // folded W + 2*B@A for q,k,v,o (16 MB)
__device__ float g_qh[BH_ * N_ * HD_];        // head-layout projections (33.5 MB each)
__device__ float g_kh[BH_ * N_ * HD_];
__device__ float g_vh[BH_ * N_ * HD_];
__device__ float g_attn[BH_ * N_ * HD_];      // accumulated attention output
__device__ int   g_sidx[3][B_][N_];           // stable sort order per (level, batch)

// ---------------- LoRA weight folding: Weff = W + 2 * B @ A ----------------
__global__ void weff_kernel(const float* __restrict__ W, const float* __restrict__ A,
                            const float* __restrict__ Bm, int which) {
    int idx = blockIdx.x * 256 + threadIdx.x;          // e*1024 + k
    int e = idx >> 10, k = idx & 1023;
    float acc = W[idx];
#pragma unroll
    for (int r = 0; r < 8; r++)
        acc = fmaf(2.0f * Bm[e * 8 + r], A[r * 1024 + k], acc);
    g_weff[which][idx] = acc;
}

// ---------------- stable argsort via bitonic sort on (bucket<<12)|pos ----------------
__global__ void sort_kernel(const int* __restrict__ wb0, const int* __restrict__ wb1,
                            const int* __restrict__ wb2) {
    int batch = blockIdx.x, level = blockIdx.y;
    const int* wb = (level == 0) ? wb0 : (level == 1) ? wb1 : wb2;
    __shared__ unsigned key[N_];
    int tid = threadIdx.x;                              // 1024 threads
    for (int i = tid; i < N_; i += 1024)
        key[i] = ((unsigned)wb[batch * N_ + i] << 12) | (unsigned)i;
    __syncthreads();
    for (int k = 2; k <= N_; k <<= 1) {
        for (int j = k >> 1; j > 0; j >>= 1) {
            for (int t = tid; t < N_; t += 1024) {
                int ixj = t ^ j;
                if (ixj > t) {
                    unsigned a = key[t], b = key[ixj];
                    bool up = ((t & k) == 0);
                    if ((a > b) == up) { key[t] = b; key[ixj] = a; }
                }
            }
            __syncthreads();
        }
    }
    for (int i = tid; i < N_; i += 1024)
        g_sidx[level][batch][i] = (int)(key[i] & 0xFFFu);
}

// ---------------- SGEMM 128x128x8, 8x8 per thread: projections into head layout ----------------
__global__ __launch_bounds__(256) void gemm_qkv(const float* __restrict__ x,
                                                const float* __restrict__ bias, int which) {
    __shared__ float As[8][128];
    __shared__ float Bs[8][128];
    float* dst = (which == 0) ? g_qh : (which == 1) ? g_kh : g_vh;
    const float* Wf = g_weff[which];
    int m0 = blockIdx.x * 128, n0 = blockIdx.y * 128;
    int tid = threadIdx.x;
    int lr = tid >> 1, lc = (tid & 1) << 2;             // load: row 0..127, col-offset 0/4
    int ty = tid >> 4, tx = tid & 15;                   // compute: 16x16 thread grid
    float c[8][8] = {};
    const float* xp = x + (size_t)(m0 + lr) * 1024 + lc;
    const float* wp = Wf + (size_t)(n0 + lr) * 1024 + lc;

    for (int k0 = 0; k0 < 1024; k0 += 8) {
        float4 a = *(const float4*)(xp + k0);
        float4 b = *(const float4*)(wp + k0);
        As[lc + 0][lr] = a.x; As[lc + 1][lr] = a.y; As[lc + 2][lr] = a.z; As[lc + 3][lr] = a.w;
        Bs[lc + 0][lr] = b.x; Bs[lc + 1][lr] = b.y; Bs[lc + 2][lr] = b.z; Bs[lc + 3][lr] = b.w;
        __syncthreads();
#pragma unroll
        for (int kk = 0; kk < 8; kk++) {
            float av[8], bv[8];
            *(float4*)&av[0] = *(const float4*)&As[kk][ty * 8];
            *(float4*)&av[4] = *(const float4*)&As[kk][ty * 8 + 4];
            *(float4*)&bv[0] = *(const float4*)&Bs[kk][tx * 8];
            *(float4*)&bv[4] = *(const float4*)&Bs[kk][tx * 8 + 4];
#pragma unroll
            for (int i = 0; i < 8; i++)
#pragma unroll
                for (int j = 0; j < 8; j++)
                    c[i][j] = fmaf(av[i], bv[j], c[i][j]);
        }
        __syncthreads();
    }
#pragma unroll
    for (int i = 0; i < 8; i++) {
        int m = m0 + ty * 8 + i;
        int bb = m >> 12, nn = m & 4095;
#pragma unroll
        for (int j = 0; j < 8; j++) {
            int n = n0 + tx * 8 + j;
            int h = n >> 6, d = n & 63;
            dst[(((size_t)(bb * H_ + h) * N_) + nn) * HD_ + d] = c[i][j] + bias[n];
        }
    }
}

// ---------------- output projection: gathers head-layout attn, writes [B,N,E] ----------------
__global__ __launch_bounds__(256) void gemm_o(const float* __restrict__ bias,
                                              float* __restrict__ out) {
    __shared__ float As[8][128];
    __shared__ float Bs[8][128];
    const float* Wf = g_weff[3];
    int m0 = blockIdx.x * 128, n0 = blockIdx.y * 128;
    int tid = threadIdx.x;
    int lr = tid >> 1, lc = (tid & 1) << 2;
    int ty = tid >> 4, tx = tid & 15;
    float c[8][8] = {};
    int mrow = m0 + lr;
    int bb = mrow >> 12, nn = mrow & 4095;
    const float* abase = g_attn + (size_t)bb * H_ * N_ * HD_ + (size_t)nn * HD_ + lc;
    const float* wp = Wf + (size_t)(n0 + lr) * 1024 + lc;

    for (int k0 = 0; k0 < 1024; k0 += 8) {
        // k = h*64 + d ; within a k-tile of 8 the head index is fixed
        float4 a = *(const float4*)(abase + (size_t)(k0 >> 6) * (N_ * HD_) + (k0 & 63));
        float4 b = *(const float4*)(wp + k0);
        As[lc + 0][lr] = a.x; As[lc + 1][lr] = a.y; As[lc + 2][lr] = a.z; As[lc + 3][lr] = a.w;
        Bs[lc + 0][lr] = b.x; Bs[lc + 1][lr] = b.y; Bs[lc + 2][lr] = b.z; Bs[lc + 3][lr] = b.w;
        __syncthreads();
#pragma unroll
        for (int kk = 0; kk < 8; kk++) {
            float av[8], bv[8];
            *(float4*)&av[0] = *(const float4*)&As[kk][ty * 8];
            *(float4*)&av[4] = *(const float4*)&As[kk][ty * 8 + 4];
            *(float4*)&bv[0] = *(const float4*)&Bs[kk][tx * 8];
            *(float4*)&bv[4] = *(const float4*)&Bs[kk][tx * 8 + 4];
#pragma unroll
            for (int i = 0; i < 8; i++)
#pragma unroll
                for (int j = 0; j < 8; j++)
                    c[i][j] = fmaf(av[i], bv[j], c[i][j]);
        }
        __syncthreads();
    }
#pragma unroll
    for (int i = 0; i < 8; i++) {
        int m = m0 + ty * 8 + i;
#pragma unroll
        for (int j = 0; j < 8; j++) {
            int n = n0 + tx * 8 + j;
            out[(size_t)m * E_ + n] = c[i][j] + bias[n];
        }
    }
}

// ---------------- chunked attention: one thread per query, streamed K/V tiles ----------------
// C = chunk size, G = chunks per block (C*G == 256). FIRST: overwrite vs accumulate.
template <int C, int G, bool FIRST>
__global__ __launch_bounds__(256) void attn_kernel(int level) {
    constexpr int TK = 64;
    __shared__ float Ks[TK][HD_];
    __shared__ float Vs[TK][HD_];
    int bh = blockIdx.x;
    int batch = bh >> 4;
    int c0 = blockIdx.y * G;
    const int* sidx = &g_sidx[level][batch][0];
    int tid = threadIdx.x;
    int g = tid / C;
    int li = tid % C;
    int chunk = c0 + g;
    int pq = chunk * C + li;                       // sorted position of this query
    int qtok = sidx[pq];
    const float* qrow = g_qh + ((size_t)bh * N_ + qtok) * HD_;

    float q[HD_], o[HD_];
#pragma unroll
    for (int d = 0; d < HD_; d += 4) {
        float4 qv = *(const float4*)(qrow + d);
        q[d] = qv.x; q[d + 1] = qv.y; q[d + 2] = qv.z; q[d + 3] = qv.w;
        o[d] = 0.f; o[d + 1] = 0.f; o[d + 2] = 0.f; o[d + 3] = 0.f;
    }
    float mmax = -1e30f, ssum = 0.f;

    int lo = (chunk == 0) ? 0 : (chunk - 1) * C;   // chunk-0 look-back is masked in reference
    int hi = (chunk + 1) * C;
    int ulo = (c0 == 0) ? 0 : (c0 - 1) * C;        // union over all chunks in this block
    int uhi = (c0 + G) * C;

    int r = tid >> 2, part = tid & 3;              // K/V tile loader mapping
    for (int t0 = ulo; t0 < uhi; t0 += TK) {
        int tn = min(TK, uhi - t0);
        if (r < tn) {
            int ktok = sidx[t0 + r];
            const float4* ksrc = (const float4*)(g_kh + ((size_t)bh * N_ + ktok) * HD_) + part * 4;
            const float4* vsrc = (const float4*)(g_vh + ((size_t)bh * N_ + ktok) * HD_) + part * 4;
            float4* kd = (float4*)&Ks[r][part * 16];
            float4* vd = (float4*)&Vs[r][part * 16];
#pragma unroll
            for (int u = 0; u < 4; u++) { kd[u] = ksrc[u]; vd[u] = vsrc[u]; }
        }
        __syncthreads();

        int jlo = max(lo, t0), jhi = min(hi, t0 + tn);
        for (int p = jlo; p < jhi; p++) {
            int jj = p - t0;
            float s0 = 0.f, s1 = 0.f, s2 = 0.f, s3 = 0.f;
#pragma unroll
            for (int d = 0; d < HD_; d += 4) {
                float4 kv = *(const float4*)&Ks[jj][d];
                s0 = fmaf(q[d],     kv.x, s0);
                s1 = fmaf(q[d + 1], kv.y, s1);
                s2 = fmaf(q[d + 2], kv.z, s2);
                s3 = fmaf(q[d + 3], kv.w, s3);
            }
            float sc = ((s0 + s1) + (s2 + s3)) * 0.125f;   // / sqrt(64)
            if (sc > mmax) {
                float corr = __expf(mmax - sc);            // first key: exp(-huge)=0
                ssum *= corr;
#pragma unroll
                for (int d = 0; d < HD_; d++) o[d] *= corr;
                mmax = sc;
            }
            float pw = __expf(sc - mmax);
            ssum += pw;
#pragma unroll
            for (int d = 0; d < HD_; d += 4) {
                float4 vv = *(const float4*)&Vs[jj][d];
                o[d]     = fmaf(pw, vv.x, o[d]);
                o[d + 1] = fmaf(pw, vv.y, o[d + 1]);
                o[d + 2] = fmaf(pw, vv.z, o[d + 2]);
                o[d + 3] = fmaf(pw, vv.w, o[d + 3]);
            }
        }
        __syncthreads();
    }

    float inv = 1.f / (3.f * ssum);                // /3 for the 3-level average
    float* dst = g_attn + ((size_t)bh * N_ + qtok) * HD_;
#pragma unroll
    for (int d = 0; d < HD_; d++) {
        float v = o[d] * inv;
        if (FIRST) dst[d] = v; else dst[d] += v;
    }
}

// ---------------- launch ----------------
extern "C" void kernel_launch(void* const* d_in, const int* in_sizes, int n_in,
                              void* d_out, int out_size) {
    (void)in_sizes; (void)n_in; (void)out_size;
    const float* x   = (const float*)d_in[0];
    const int*   wbc = (const int*)d_in[1];
    const int*   wbm = (const int*)d_in[2];
    const int*   wbf = (const int*)d_in[3];
    const float* Wp[4] = { (const float*)d_in[4],  (const float*)d_in[8],
                           (const float*)d_in[12], (const float*)d_in[16] };
    const float* bp[4] = { (const float*)d_in[5],  (const float*)d_in[9],
                           (const float*)d_in[13], (const float*)d_in[17] };
    const float* Ap[4] = { (const float*)d_in[6],  (const float*)d_in[10],
                           (const float*)d_in[14], (const float*)d_in[18] };
    const float* Lp[4] = { (const float*)d_in[7],  (const float*)d_in[11],
                           (const float*)d_in[15], (const float*)d_in[19] };
    float* out = (float*)d_out;

    // 1) fold LoRA into effective weights
    for (int p = 0; p < 4; p++)
        weff_kernel<<<(E_ * E_) / 256, 256>>>(Wp[p], Ap[p], Lp[p], p);

    // 2) stable argsort per (batch, level)
    sort_kernel<<<dim3(B_, 3), 1024>>>(wbc, wbm, wbf);

    // 3) q,k,v projections into head layout
    for (int p = 0; p < 3; p++)
        gemm_qkv<<<dim3(M_ / 128, E_ / 128), 256>>>(x, bp[p], p);

    // 4) three-level chunked attention, accumulated into g_attn
    attn_kernel<256, 1,  true ><<<dim3(BH_, 16), 256>>>(0);
    attn_kernel<64,  4,  false><<<dim3(BH_, 16), 256>>>(1);
    attn_kernel<16,  16, false><<<dim3(BH_, 16), 256>>>(2);

    // 5) output projection
    gemm_o<<<dim3(M_ / 128, E_ / 128), 256>>>(bp[3], out);
}

// round 3
// speedup vs baseline: 1.8389x; 1.8389x over previous
#include <cuda_runtime.h>
#include <cuda_bf16.h>
#include <math.h>
#include <stdint.h>

#define B_   2
#define N_   4096
#define E_   1024
#define H_   16
#define HD_  64
#define BH_  32
#define M_   8192

// ==================== device scratch ====================
__device__ __align__(16) __nv_bfloat16 g_whi[4][E_ * E_];
__device__ __align__(16) __nv_bfloat16 g_wlo[4][E_ * E_];
__device__ __align__(16) __nv_bfloat16 g_xhi[M_ * E_];
__device__ __align__(16) __nv_bfloat16 g_xlo[M_ * E_];
__device__ __align__(16) __nv_bfloat16 g_ahi[M_ * E_];
__device__ __align__(16) __nv_bfloat16 g_alo[M_ * E_];
__device__ float g_q[M_ * E_];
__device__ float g_k[M_ * E_];
__device__ float g_v[M_ * E_];
__device__ float g_attn[M_ * E_];
__device__ int   g_sidx[3][B_][N_];

// ==================== helpers ====================
__device__ __forceinline__ uint32_t smem_u32(const void* p) {
    uint32_t a;
    asm("{ .reg .u64 t; cvta.to.shared.u64 t, %1; cvt.u32.u64 %0, t; }" : "=r"(a) : "l"(p));
    return a;
}
__device__ __forceinline__ void cp16(uint32_t dst, const void* src) {
    asm volatile("cp.async.cg.shared.global [%0], [%1], 16;" :: "r"(dst), "l"(src));
}
#define CP_COMMIT() asm volatile("cp.async.commit_group;" ::: "memory")
#define CP_WAIT(n)  asm volatile("cp.async.wait_group %0;" :: "n"(n) : "memory")

__device__ __forceinline__ void mma16816(float* c, uint32_t a0, uint32_t a1, uint32_t a2,
                                         uint32_t a3, uint32_t b0, uint32_t b1) {
    asm volatile(
        "mma.sync.aligned.m16n8k16.row.col.f32.bf16.bf16.f32 "
        "{%0,%1,%2,%3}, {%4,%5,%6,%7}, {%8,%9}, {%0,%1,%2,%3};"
        : "+f"(c[0]), "+f"(c[1]), "+f"(c[2]), "+f"(c[3])
        : "r"(a0), "r"(a1), "r"(a2), "r"(a3), "r"(b0), "r"(b1));
}

// ==================== LoRA fold + bf16 hi/lo split ====================
__global__ void weff_kernel(const float* __restrict__ W, const float* __restrict__ A,
                            const float* __restrict__ Bm, int which) {
    int idx = blockIdx.x * 256 + threadIdx.x;
    int e = idx >> 10, k = idx & 1023;
    float acc = W[idx];
#pragma unroll
    for (int r = 0; r < 8; r++)
        acc = fmaf(2.0f * Bm[e * 8 + r], A[r * 1024 + k], acc);
    __nv_bfloat16 hi = __float2bfloat16_rn(acc);
    __nv_bfloat16 lo = __float2bfloat16_rn(acc - __bfloat162float(hi));
    g_whi[which][idx] = hi;
    g_wlo[which][idx] = lo;
}

// ==================== fp32 -> bf16 hi/lo conversion (x or attn) ====================
__global__ void cvt_kernel(const float* __restrict__ xsrc, int sel) {
    const float* src = sel ? g_attn : xsrc;
    __nv_bfloat16* hi = sel ? g_ahi : g_xhi;
    __nv_bfloat16* lo = sel ? g_alo : g_xlo;
    int i = blockIdx.x * 256 + threadIdx.x;
    float4 v = ((const float4*)src)[i];
    __nv_bfloat16 hx = __float2bfloat16_rn(v.x), hy = __float2bfloat16_rn(v.y);
    __nv_bfloat16 hz = __float2bfloat16_rn(v.z), hw = __float2bfloat16_rn(v.w);
    __nv_bfloat16 lx = __float2bfloat16_rn(v.x - __bfloat162float(hx));
    __nv_bfloat16 ly = __float2bfloat16_rn(v.y - __bfloat162float(hy));
    __nv_bfloat16 lz = __float2bfloat16_rn(v.z - __bfloat162float(hz));
    __nv_bfloat16 lw = __float2bfloat16_rn(v.w - __bfloat162float(hw));
    __nv_bfloat162* hp = (__nv_bfloat162*)hi + 2 * i;
    __nv_bfloat162* lp = (__nv_bfloat162*)lo + 2 * i;
    hp[0] = __halves2bfloat162(hx, hy); hp[1] = __halves2bfloat162(hz, hw);
    lp[0] = __halves2bfloat162(lx, ly); lp[1] = __halves2bfloat162(lz, lw);
}

// ==================== stable argsort (bitonic on (bucket<<12)|pos) ====================
__global__ void sort_kernel(const int* __restrict__ wb0, const int* __restrict__ wb1,
                            const int* __restrict__ wb2) {
    int batch = blockIdx.x, level = blockIdx.y;
    const int* wb = (level == 0) ? wb0 : (level == 1) ? wb1 : wb2;
    __shared__ unsigned key[N_];
    int tid = threadIdx.x;
    for (int i = tid; i < N_; i += 1024)
        key[i] = ((unsigned)wb[batch * N_ + i] << 12) | (unsigned)i;
    __syncthreads();
    for (int k = 2; k <= N_; k <<= 1) {
        for (int j = k >> 1; j > 0; j >>= 1) {
            for (int t = tid; t < N_; t += 1024) {
                int ixj = t ^ j;
                if (ixj > t) {
                    unsigned a = key[t], b = key[ixj];
                    bool up = ((t & k) == 0);
                    if ((a > b) == up) { key[t] = b; key[ixj] = a; }
                }
            }
            __syncthreads();
        }
    }
    for (int i = tid; i < N_; i += 1024)
        g_sidx[level][batch][i] = (int)(key[i] & 0xFFFu);
}

// ==================== HMMA bf16-split GEMM: out[M,1024] = A @ W^T + bias ====================
// CTA tile 128x128, K-chunks of 64; smem tiles: Ahi, Alo, Bhi, Blo (16KB each), double buffered.
static constexpr int TILEB = 128 * 128;                 // bytes per tile (128 rows x 128B)
static constexpr int BUFB  = 4 * TILEB;                 // 64KB per buffer
static constexpr int GEMM_SMEM = 2 * BUFB;              // 128KB

// swizzled smem byte offset for (row, bf16 col)
__device__ __forceinline__ uint32_t swoff(int row, int col) {
    return (uint32_t)(row * 128 + ((col * 2) ^ ((row & 7) << 4)));
}

__global__ __launch_bounds__(256, 1) void gemm_tc(int asel, int bsel, int osel,
                                                  const float* __restrict__ bias,
                                                  float* __restrict__ out_ext) {
    extern __shared__ __align__(16) char dsm[];
    const __nv_bfloat16* Ahi = asel ? g_ahi : g_xhi;
    const __nv_bfloat16* Alo = asel ? g_alo : g_xlo;
    const __nv_bfloat16* Bhi = g_whi[bsel];
    const __nv_bfloat16* Blo = g_wlo[bsel];
    float* out = (osel == 0) ? g_q : (osel == 1) ? g_k : (osel == 2) ? g_v : out_ext;

    int tid = threadIdx.x;
    int wid = tid >> 5, lane = tid & 31;
    int g = lane >> 2, t = lane & 3;
    int wm = wid >> 2, wn = wid & 3;                    // warp grid 2x4
    int m0 = blockIdx.x * 128, n0 = blockIdx.y * 128;

    uint32_t sbase = smem_u32(dsm);
    const __nv_bfloat16* srcs[4] = {
        Ahi + (size_t)m0 * E_, Alo + (size_t)m0 * E_,
        Bhi + (size_t)n0 * E_, Blo + (size_t)n0 * E_ };

    int lrow = tid >> 3, lch = tid & 7;                 // 256 threads -> 32 rows x 8 chunks

    // issue loads for chunk kc into buffer b
    auto load_chunk = [&](int b, int kc) {
#pragma unroll
        for (int tgt = 0; tgt < 4; tgt++) {
            uint32_t tb = sbase + b * BUFB + tgt * TILEB;
            const __nv_bfloat16* s = srcs[tgt] + kc * 64 + lch * 8;
#pragma unroll
            for (int p = 0; p < 4; p++) {
                int row = p * 32 + lrow;
                cp16(tb + row * 128 + (((uint32_t)(lch * 16)) ^ ((uint32_t)(row & 7) << 4)),
                     s + (size_t)row * E_);
            }
        }
        CP_COMMIT();
    };

    float acc[4][4][4];
#pragma unroll
    for (int i = 0; i < 4; i++)
#pragma unroll
        for (int j = 0; j < 4; j++)
#pragma unroll
            for (int q = 0; q < 4; q++) acc[i][j][q] = 0.f;

    load_chunk(0, 0);

    for (int kc = 0; kc < 16; kc++) {
        int b = kc & 1;
        if (kc + 1 < 16) { load_chunk(b ^ 1, kc + 1); CP_WAIT(1); }
        else             { CP_WAIT(0); }
        __syncthreads();

        const char* bufA = dsm + b * BUFB;
        const char* bufAl = bufA + TILEB;
        const char* bufB = bufA + 2 * TILEB;
        const char* bufBl = bufA + 3 * TILEB;

#pragma unroll
        for (int ks = 0; ks < 4; ks++) {
            int ko = ks * 16;
            uint32_t ah[4][4], al[4][4], bh[4][2], bl[4][2];
#pragma unroll
            for (int mi = 0; mi < 4; mi++) {
                int r0 = wm * 64 + mi * 16 + g;
                ah[mi][0] = *(const uint32_t*)(bufA  + swoff(r0,     ko + 2 * t));
                ah[mi][1] = *(const uint32_t*)(bufA  + swoff(r0 + 8, ko + 2 * t));
                ah[mi][2] = *(const uint32_t*)(bufA  + swoff(r0,     ko + 8 + 2 * t));
                ah[mi][3] = *(const uint32_t*)(bufA  + swoff(r0 + 8, ko + 8 + 2 * t));
                al[mi][0] = *(const uint32_t*)(bufAl + swoff(r0,     ko + 2 * t));
                al[mi][1] = *(const uint32_t*)(bufAl + swoff(r0 + 8, ko + 2 * t));
                al[mi][2] = *(const uint32_t*)(bufAl + swoff(r0,     ko + 8 + 2 * t));
                al[mi][3] = *(const uint32_t*)(bufAl + swoff(r0 + 8, ko + 8 + 2 * t));
            }
#pragma unroll
            for (int ni = 0; ni < 4; ni++) {
                int rn = wn * 32 + ni * 8 + g;
                bh[ni][0] = *(const uint32_t*)(bufB  + swoff(rn, ko + 2 * t));
                bh[ni][1] = *(const uint32_t*)(bufB  + swoff(rn, ko + 8 + 2 * t));
                bl[ni][0] = *(const uint32_t*)(bufBl + swoff(rn, ko + 2 * t));
                bl[ni][1] = *(const uint32_t*)(bufBl + swoff(rn, ko + 8 + 2 * t));
            }
#pragma unroll
            for (int mi = 0; mi < 4; mi++)
#pragma unroll
                for (int ni = 0; ni < 4; ni++)
                    mma16816(acc[mi][ni], ah[mi][0], ah[mi][1], ah[mi][2], ah[mi][3],
                             bh[ni][0], bh[ni][1]);
#pragma unroll
            for (int mi = 0; mi < 4; mi++)
#pragma unroll
                for (int ni = 0; ni < 4; ni++)
                    mma16816(acc[mi][ni], ah[mi][0], ah[mi][1], ah[mi][2], ah[mi][3],
                             bl[ni][0], bl[ni][1]);
#pragma unroll
            for (int mi = 0; mi < 4; mi++)
#pragma unroll
                for (int ni = 0; ni < 4; ni++)
                    mma16816(acc[mi][ni], al[mi][0], al[mi][1], al[mi][2], al[mi][3],
                             bh[ni][0], bh[ni][1]);
        }
        __syncthreads();
    }

    // epilogue: add bias, write fp32
#pragma unroll
    for (int mi = 0; mi < 4; mi++) {
        int r0 = m0 + wm * 64 + mi * 16 + g;
#pragma unroll
        for (int ni = 0; ni < 4; ni++) {
            int col = n0 + wn * 32 + ni * 8 + 2 * t;
            float bx = bias[col], by = bias[col + 1];
            float2 v0 = { acc[mi][ni][0] + bx, acc[mi][ni][1] + by };
            float2 v1 = { acc[mi][ni][2] + bx, acc[mi][ni][3] + by };
            *(float2*)(out + (size_t)r0 * E_ + col) = v0;
            *(float2*)(out + (size_t)(r0 + 8) * E_ + col) = v1;
        }
    }
}

// ==================== chunked attention (scalar fp32, known-good) ====================
template <int C, int G, bool FIRST>
__global__ __launch_bounds__(256) void attn_kernel(int level) {
    constexpr int TK = 64;
    __shared__ float Ks[TK][HD_];
    __shared__ float Vs[TK][HD_];
    int bh = blockIdx.x;
    int batch = bh >> 4, h = bh & 15;
    int c0 = blockIdx.y * G;
    const int* sidx = &g_sidx[level][batch][0];
    int tid = threadIdx.x;
    int g = tid / C, li = tid % C;
    int chunk = c0 + g;
    int pq = chunk * C + li;
    int qtok = sidx[pq];
    size_t rowbase = ((size_t)(batch * N_ + qtok)) * E_ + h * HD_;
    const float* qrow = g_q + rowbase;

    float q[HD_], o[HD_];
#pragma unroll
    for (int d = 0; d < HD_; d += 4) {
        float4 qv = *(const float4*)(qrow + d);
        q[d] = qv.x; q[d + 1] = qv.y; q[d + 2] = qv.z; q[d + 3] = qv.w;
        o[d] = 0.f; o[d + 1] = 0.f; o[d + 2] = 0.f; o[d + 3] = 0.f;
    }
    float mmax = -1e30f, ssum = 0.f;

    int lo = (chunk == 0) ? 0 : (chunk - 1) * C;
    int hi = (chunk + 1) * C;
    int ulo = (c0 == 0) ? 0 : (c0 - 1) * C;
    int uhi = (c0 + G) * C;

    int r = tid >> 2, part = tid & 3;
    for (int t0 = ulo; t0 < uhi; t0 += TK) {
        int tn = min(TK, uhi - t0);
        if (r < tn) {
            int ktok = sidx[t0 + r];
            size_t kb = ((size_t)(batch * N_ + ktok)) * E_ + h * HD_;
            const float4* ksrc = (const float4*)(g_k + kb) + part * 4;
            const float4* vsrc = (const float4*)(g_v + kb) + part * 4;
            float4* kd = (float4*)&Ks[r][part * 16];
            float4* vd = (float4*)&Vs[r][part * 16];
#pragma unroll
            for (int u = 0; u < 4; u++) { kd[u] = ksrc[u]; vd[u] = vsrc[u]; }
        }
        __syncthreads();

        int jlo = max(lo, t0), jhi = min(hi, t0 + tn);
        for (int p = jlo; p < jhi; p++) {
            int jj = p - t0;
            float s0 = 0.f, s1 = 0.f, s2 = 0.f, s3 = 0.f;
#pragma unroll
            for (int d = 0; d < HD_; d += 4) {
                float4 kv = *(const float4*)&Ks[jj][d];
                s0 = fmaf(q[d],     kv.x, s0);
                s1 = fmaf(q[d + 1], kv.y, s1);
                s2 = fmaf(q[d + 2], kv.z, s2);
                s3 = fmaf(q[d + 3], kv.w, s3);
            }
            float sc = ((s0 + s1) + (s2 + s3)) * 0.125f;
            if (sc > mmax) {
                float corr = __expf(mmax - sc);
                ssum *= corr;
#pragma unroll
                for (int d = 0; d < HD_; d++) o[d] *= corr;
                mmax = sc;
            }
            float pw = __expf(sc - mmax);
            ssum += pw;
#pragma unroll
            for (int d = 0; d < HD_; d += 4) {
                float4 vv = *(const float4*)&Vs[jj][d];
                o[d]     = fmaf(pw, vv.x, o[d]);
                o[d + 1] = fmaf(pw, vv.y, o[d + 1]);
                o[d + 2] = fmaf(pw, vv.z, o[d + 2]);
                o[d + 3] = fmaf(pw, vv.w, o[d + 3]);
            }
        }
        __syncthreads();
    }

    float inv = 1.f / (3.f * ssum);
    float* dst = g_attn + rowbase;
#pragma unroll
    for (int d = 0; d < HD_; d++) {
        float v = o[d] * inv;
        if (FIRST) dst[d] = v; else dst[d] += v;
    }
}

// ==================== launch ====================
extern "C" void kernel_launch(void* const* d_in, const int* in_sizes, int n_in,
                              void* d_out, int out_size) {
    (void)in_sizes; (void)n_in; (void)out_size;
    const float* x   = (const float*)d_in[0];
    const int*   wbc = (const int*)d_in[1];
    const int*   wbm = (const int*)d_in[2];
    const int*   wbf = (const int*)d_in[3];
    const float* Wp[4] = { (const float*)d_in[4],  (const float*)d_in[8],
                           (const float*)d_in[12], (const float*)d_in[16] };
    const float* bp[4] = { (const float*)d_in[5],  (const float*)d_in[9],
                           (const float*)d_in[13], (const float*)d_in[17] };
    const float* Ap[4] = { (const float*)d_in[6],  (const float*)d_in[10],
                           (const float*)d_in[14], (const float*)d_in[18] };
    const float* Lp[4] = { (const float*)d_in[7],  (const float*)d_in[11],
                           (const float*)d_in[15], (const float*)d_in[19] };
    float* out = (float*)d_out;

    cudaFuncSetAttribute(gemm_tc, cudaFuncAttributeMaxDynamicSharedMemorySize, GEMM_SMEM);

    // 1) fold LoRA + split weights to bf16 hi/lo
    for (int p = 0; p < 4; p++)
        weff_kernel<<<(E_ * E_) / 256, 256>>>(Wp[p], Ap[p], Lp[p], p);

    // 2) split x to bf16 hi/lo
    cvt_kernel<<<(M_ * E_ / 4) / 256, 256>>>(x, 0);

    // 3) stable argsort per (batch, level)
    sort_kernel<<<dim3(B_, 3), 1024>>>(wbc, wbm, wbf);

    // 4) q,k,v projections (tensor cores via mma.sync)
    for (int p = 0; p < 3; p++)
        gemm_tc<<<dim3(M_ / 128, E_ / 128), 256, GEMM_SMEM>>>(0, p, p, bp[p], nullptr);

    // 5) three-level chunked attention
    attn_kernel<256, 1,  true ><<<dim3(BH_, 16), 256>>>(0);
    attn_kernel<64,  4,  false><<<dim3(BH_, 16), 256>>>(1);
    attn_kernel<16,  16, false><<<dim3(BH_, 16), 256>>>(2);

    // 6) split attention output to bf16 hi/lo
    cvt_kernel<<<(M_ * E_ / 4) / 256, 256>>>(nullptr, 1);

    // 7) output projection
    gemm_tc<<<dim3(M_ / 128, E_ / 128), 256, GEMM_SMEM>>>(1, 3, 3, bp[3], out);
}